// round 1
// baseline (speedup 1.0000x reference)
#include <cuda_runtime.h>
#include <cstdint>

// SocialPooling fused kernel (fp32, f32x2-packed FFMA).
// Fixed problem shape: HIDDEN=128, PEDS=64/scene, G=4 (16 cells), POOL=64,
// NBHD=2.0 -> scale = G/(2*NBHD) = 1.0 exactly.
//
// One CTA per scene:
//   1. hidden tile [64x128] + positions -> smem
//   2. CSR neighbor lists per (ped, cell)  (exact same fp32 cell math as ref)
//   3. for each of 16 cells: build pooled S_g transposed [128k x 66] in smem,
//      stage W_g [128x64] in smem, accumulate out[64x64] in registers with
//      fma.rn.f32x2 (rows paired in the packed lanes).
//   4. out = bias + sum_g S_g @ W_g

#define HID   128
#define PED   64
#define NCELL 16
#define POOLN 64
#define TPB   256
#define SGT_STRIDE 66   // padded transposed-S stride (keeps 8B align + spreads banks)

__device__ __forceinline__ unsigned long long pack2(float v) {
    unsigned long long r;
    asm("mov.b64 %0, {%1, %1};" : "=l"(r) : "r"(__float_as_uint(v)));
    return r;
}

__device__ __forceinline__ void ffma2(unsigned long long& acc,
                                      unsigned long long a,
                                      unsigned long long b) {
    // packed fp32x2 FMA (sm_100+): acc = a*b + acc, lanewise
    asm("fma.rn.f32x2 %0, %1, %2, %0;" : "+l"(acc) : "l"(a), "l"(b));
}

// Cell index matching the reference exactly (fp32 ops in same order).
// Returns -1 if masked (self or out of neighborhood).
__device__ __forceinline__ int cell_of(float xi, float yi, float xj, float yj, bool self) {
    float dx = xj - xi;
    float dy = yj - yi;
    if (self || fabsf(dx) > 2.0f || fabsf(dy) > 2.0f) return -1;
    // scale = 1.0f exactly -> multiply is identity
    int gx = (int)floorf(dx + 2.0f);
    int gy = (int)floorf(dy + 2.0f);
    gx = max(0, min(3, gx));
    gy = max(0, min(3, gy));
    return gy * 4 + gx;
}

__global__ __launch_bounds__(TPB, 2)
void social_pool_kernel(const float* __restrict__ hidden,
                        const float* __restrict__ pos,
                        const float* __restrict__ weight,
                        const float* __restrict__ bias,
                        float* __restrict__ out)
{
    extern __shared__ char smem_raw[];
    float* sh  = (float*)smem_raw;                 // [64][128] hidden tile (32 KB)
    float* sgT = sh + PED * HID;                   // [128][66] pooled S, transposed (33 KB)
    float* sw  = sgT + HID * SGT_STRIDE;           // [128][64] W_g tile (32 KB)
    float* px  = sw + HID * POOLN;                 // [64]
    float* py  = px + PED;                         // [64]
    unsigned short* joff = (unsigned short*)(py + PED);      // [64][17] CSR offsets
    unsigned short* scnt = joff + PED * 17;                  // [64][16] counters
    unsigned char*  jlist = (unsigned char*)(scnt + PED * NCELL); // [64][64] neighbor ids

    const int tid  = threadIdx.x;
    const int b    = blockIdx.x;
    const int lane = tid & 31;
    const int warp = tid >> 5;

    // ---- load hidden tile + positions ----
    {
        const float4* gh4 = (const float4*)(hidden + (size_t)b * PED * HID);
        float4* sh4 = (float4*)sh;
        #pragma unroll
        for (int r = 0; r < (PED * HID / 4) / TPB; r++)
            sh4[tid + r * TPB] = gh4[tid + r * TPB];
    }
    if (tid < PED) {
        px[tid] = pos[((size_t)b * PED + tid) * 2 + 0];
        py[tid] = pos[((size_t)b * PED + tid) * 2 + 1];
    }
    __syncthreads();

    // ---- CSR neighbor lists: per ped i, j's bucketed by cell ----
    if (tid < PED) {
        const int i = tid;
        const float xi = px[i], yi = py[i];
        #pragma unroll
        for (int c = 0; c < NCELL; c++) scnt[i * NCELL + c] = 0;
        for (int j = 0; j < PED; j++) {
            int c = cell_of(xi, yi, px[j], py[j], j == i);
            if (c >= 0) scnt[i * NCELL + c]++;
        }
        unsigned short run = 0;
        #pragma unroll
        for (int c = 0; c < NCELL; c++) {
            joff[i * 17 + c] = run;
            run = (unsigned short)(run + scnt[i * NCELL + c]);
            scnt[i * NCELL + c] = 0;
        }
        joff[i * 17 + 16] = run;
        for (int j = 0; j < PED; j++) {
            int c = cell_of(xi, yi, px[j], py[j], j == i);
            if (c >= 0) {
                int slot = joff[i * 17 + c] + scnt[i * NCELL + c]++;
                jlist[i * 64 + slot] = (unsigned char)j;
            }
        }
    }

    // ---- GEMM thread mapping ----
    // thread -> (output column n, row-pair group grp). acc[m] holds the packed
    // pair (out[i0][n], out[i0+1][n]) with i0 = grp*16 + 2m.
    const int n   = tid & 63;
    const int grp = tid >> 6;   // 0..3

    unsigned long long acc[8];
    {
        unsigned long long bp = pack2(bias[n]);
        #pragma unroll
        for (int m = 0; m < 8; m++) acc[m] = bp;
    }

    const float4* sh4 = (const float4*)sh;

    for (int g = 0; g < NCELL; g++) {
        __syncthreads();  // prev GEMM done reading sgT/sw; first iter: CSR done

        // ---- build pooled S_g, transposed: sgT[k][i] ----
        // warp w owns rows i = w*8 .. w*8+7; lane covers k = lane*4 .. lane*4+3
        #pragma unroll
        for (int r = 0; r < 8; r++) {
            const int i  = warp * 8 + r;
            const int s0 = joff[i * 17 + g];
            const int s1 = joff[i * 17 + g + 1];
            float4 a = make_float4(0.f, 0.f, 0.f, 0.f);
            for (int t = s0; t < s1; t++) {
                int j = jlist[i * 64 + t];           // warp-uniform broadcast
                float4 hv = sh4[j * 32 + lane];
                a.x += hv.x; a.y += hv.y; a.z += hv.z; a.w += hv.w;
            }
            const int k0 = lane * 4;
            sgT[(k0 + 0) * SGT_STRIDE + i] = a.x;
            sgT[(k0 + 1) * SGT_STRIDE + i] = a.y;
            sgT[(k0 + 2) * SGT_STRIDE + i] = a.z;
            sgT[(k0 + 3) * SGT_STRIDE + i] = a.w;
        }

        // ---- stage W_g into smem ----
        {
            const float4* gw4 = (const float4*)(weight + (size_t)g * HID * POOLN);
            float4* sw4 = (float4*)sw;
            #pragma unroll
            for (int r = 0; r < (HID * POOLN / 4) / TPB; r++)
                sw4[tid + r * TPB] = gw4[tid + r * TPB];
        }
        __syncthreads();

        // ---- accumulate: out[i][n] += sum_k S[i][k] * W_g[k][n] ----
        #pragma unroll 2
        for (int k = 0; k < HID; k++) {
            const unsigned long long wp = pack2(sw[k * POOLN + n]);
            const float* srow = sgT + k * SGT_STRIDE + grp * 16;
            #pragma unroll
            for (int m = 0; m < 8; m++) {
                // packed pair of adjacent rows (broadcast LDS.64 within warp)
                unsigned long long s2 =
                    *(const unsigned long long*)(srow + 2 * m);
                ffma2(acc[m], s2, wp);
            }
        }
    }

    // ---- store ----
    float* orow = out + (size_t)b * PED * POOLN;
    #pragma unroll
    for (int m = 0; m < 8; m++) {
        float2 v = *(float2*)&acc[m];     // low word = even row
        const int i0 = grp * 16 + 2 * m;
        orow[(size_t)(i0 + 0) * POOLN + n] = v.x;
        orow[(size_t)(i0 + 1) * POOLN + n] = v.y;
    }
}

extern "C" void kernel_launch(void* const* d_in, const int* in_sizes, int n_in,
                              void* d_out, int out_size)
{
    const float* hidden = (const float*)d_in[0];
    const float* pos    = (const float*)d_in[1];
    const float* weight = (const float*)d_in[2];
    const float* bias   = (const float*)d_in[3];
    // d_in[4] = peds_per_scene (device scalar); shape is fixed at 64 for this problem.
    float* out = (float*)d_out;

    const int total = in_sizes[0] / HID;   // 16384 rows
    const int B     = total / PED;         // 256 scenes

    const size_t smem_bytes =
        (size_t)(PED * HID + HID * SGT_STRIDE + HID * POOLN + 2 * PED) * sizeof(float)
        + (size_t)(PED * 17 + PED * NCELL) * sizeof(unsigned short)
        + (size_t)(PED * PED) * sizeof(unsigned char);

    cudaFuncSetAttribute(social_pool_kernel,
                         cudaFuncAttributeMaxDynamicSharedMemorySize,
                         (int)smem_bytes);

    social_pool_kernel<<<B, TPB, smem_bytes>>>(hidden, pos, weight, bias, out);
}

// round 3
// speedup vs baseline: 7.8947x; 7.8947x over previous
#include <cuda_runtime.h>
#include <cuda_bf16.h>
#include <cstdint>

// SocialPooling as two chained tensor-core GEMMs (mma.sync bf16, sm_80+ PTX —
// the harness PTX target is plain sm_103, so no tcgen05).
//   stage1: S_g[128x128] = M_g[128x64(0/1)] @ (H_hi + H_lo)   (M exact in bf16)
//   stage2: out[128x64] += (S_hi @ W_hi) + (S_hi @ W_lo) + (S_lo @ W_hi)
// S stays in registers: stage1 C-fragment layout == stage2 A-fragment layout.
// Per-cell emptiness flags (runtime) skip empty cells.

#define TPB 256

#define SM_HHI  0        // bf16 [128 row][128 h], swizzled, 32 KB
#define SM_HLO  32768    // 32 KB
#define SM_PX   65536    // float[128]
#define SM_PY   66048    // float[128]
#define SM_BM   66560    // u64 [16 cell][128 row] = 16 KB
#define SM_FLAG 82944    // u32[16]
#define SMEM_TOTAL 83072

// W fragments: [g][k16][n8][lane] uint4 = {Whi.b0, Whi.b1, Wlo.b0, Wlo.b1}
__device__ uint4 g_wfrags[16 * 8 * 8 * 32];

__device__ __forceinline__ uint32_t smem_u32(const void* p) {
    uint32_t a;
    asm("{ .reg .u64 t; cvta.to.shared.u64 t, %1; cvt.u32.u64 %0, t; }" : "=r"(a) : "l"(p));
    return a;
}
// pack two fp32 -> bf16x2 (lo in low half)
__device__ __forceinline__ uint32_t pack_bf16x2(float lo, float hi) {
    uint32_t r;
    asm("cvt.rn.satfinite.bf16x2.f32 %0, %1, %2;" : "=r"(r) : "f"(hi), "f"(lo));
    return r;
}
__device__ __forceinline__ float bflo(uint32_t p) { return __uint_as_float(p << 16); }
__device__ __forceinline__ float bfhi(uint32_t p) { return __uint_as_float(p & 0xFFFF0000u); }

// two mask bits -> packed bf16x2 of {0.0 or 1.0}
__device__ __forceinline__ uint32_t mbits(unsigned long long v) {
    uint32_t r = (v & 1ull) ? 0x3F80u : 0u;
    if (v & 2ull) r |= 0x3F800000u;
    return r;
}

#define LDMX4T(r0, r1, r2, r3, addr) \
    asm volatile("ldmatrix.sync.aligned.m8n8.x4.trans.shared.b16 {%0,%1,%2,%3}, [%4];" \
                 : "=r"(r0), "=r"(r1), "=r"(r2), "=r"(r3) : "r"(addr))

#define MMA_BF16(d, a0, a1, a2, a3, b0, b1) \
    asm volatile("mma.sync.aligned.m16n8k16.row.col.f32.bf16.bf16.f32 " \
                 "{%0,%1,%2,%3}, {%4,%5,%6,%7}, {%8,%9}, {%0,%1,%2,%3};" \
                 : "+f"((d)[0]), "+f"((d)[1]), "+f"((d)[2]), "+f"((d)[3]) \
                 : "r"(a0), "r"(a1), "r"(a2), "r"(a3), "r"(b0), "r"(b1))

// ---------------- W prep: fragment-order hi/lo split ----------------
__global__ void sp_wprep(const float* __restrict__ weight) {
    int idx  = blockIdx.x * 256 + threadIdx.x;   // 32768
    int lane = idx & 31;
    int n8   = (idx >> 5) & 7;
    int k16  = (idx >> 8) & 7;
    int g    = idx >> 11;
    int n  = n8 * 8 + (lane >> 2);
    int k0 = g * 128 + k16 * 16 + (lane & 3) * 2;
    float w00 = weight[(size_t)(k0 + 0) * 64 + n];
    float w01 = weight[(size_t)(k0 + 1) * 64 + n];
    float w10 = weight[(size_t)(k0 + 8) * 64 + n];
    float w11 = weight[(size_t)(k0 + 9) * 64 + n];
    uint32_t h0 = pack_bf16x2(w00, w01);
    uint32_t h1 = pack_bf16x2(w10, w11);
    uint32_t l0 = pack_bf16x2(w00 - bflo(h0), w01 - bfhi(h0));
    uint32_t l1 = pack_bf16x2(w10 - bflo(h1), w11 - bfhi(h1));
    g_wfrags[idx] = make_uint4(h0, h1, l0, l1);
}

// ---------------- main kernel: one CTA = 2 scenes (128 rows) ----------------
__global__ __launch_bounds__(TPB, 1)
void sp_main(const float* __restrict__ hidden,
             const float* __restrict__ pos,
             const float* __restrict__ bias,
             float* __restrict__ out)
{
    extern __shared__ char smem[];
    const int tid  = threadIdx.x;
    const int lane = tid & 31;
    const int wid  = tid >> 5;
    const int b    = blockIdx.x;

    float* px = (float*)(smem + SM_PX);
    float* py = (float*)(smem + SM_PY);
    unsigned long long* bm = (unsigned long long*)(smem + SM_BM);
    uint32_t* flag = (uint32_t*)(smem + SM_FLAG);

    if (tid < 128) {
        px[tid] = pos[((size_t)b * 128 + tid) * 2 + 0];
        py[tid] = pos[((size_t)b * 128 + tid) * 2 + 1];
    }
    #pragma unroll
    for (int it = 0; it < 8; it++) bm[tid + it * 256] = 0ull;

    // H -> smem bf16 hi/lo, rows of 256B, 16B-chunk XOR swizzle
    #pragma unroll
    for (int it = 0; it < 8; it++) {
        int cid = tid + it * 256;          // 0..2047 = row*16 + chunk
        int row = cid >> 4;
        int ch  = cid & 15;
        const float4* src = (const float4*)(hidden + ((size_t)b * 128 + row) * 128 + ch * 8);
        float4 v0 = src[0], v1 = src[1];
        uint32_t h0 = pack_bf16x2(v0.x, v0.y);
        uint32_t h1 = pack_bf16x2(v0.z, v0.w);
        uint32_t h2 = pack_bf16x2(v1.x, v1.y);
        uint32_t h3 = pack_bf16x2(v1.z, v1.w);
        uint32_t l0 = pack_bf16x2(v0.x - bflo(h0), v0.y - bfhi(h0));
        uint32_t l1 = pack_bf16x2(v0.z - bflo(h1), v0.w - bfhi(h1));
        uint32_t l2 = pack_bf16x2(v1.x - bflo(h2), v1.y - bfhi(h2));
        uint32_t l3 = pack_bf16x2(v1.z - bflo(h3), v1.w - bfhi(h3));
        uint32_t off = (uint32_t)(row * 256 + ((ch ^ (row & 7)) << 4));
        *(uint4*)(smem + SM_HHI + off) = make_uint4(h0, h1, h2, h3);
        *(uint4*)(smem + SM_HLO + off) = make_uint4(l0, l1, l2, l3);
    }
    __syncthreads();

    // neighbor bitmasks per (cell, row) — exact reference cell math
    if (tid < 128) {
        const int i = tid;
        const int sb = i & 64;
        const float xi = px[i], yi = py[i];
        for (int j = 0; j < 64; j++) {
            int jj = sb + j;
            float dx = px[jj] - xi, dy = py[jj] - yi;
            if (jj != i && fabsf(dx) <= 2.0f && fabsf(dy) <= 2.0f) {
                int gx = min(3, max(0, (int)floorf(dx + 2.0f)));
                int gy = min(3, max(0, (int)floorf(dy + 2.0f)));
                bm[(gy * 4 + gx) * 128 + i] |= (1ull << j);
            }
        }
    }
    __syncthreads();
    if (tid < 16) {
        unsigned long long o = 0;
        #pragma unroll 8
        for (int i = 0; i < 128; i++) o |= bm[tid * 128 + i];
        flag[tid] = (o != 0ull) ? 1u : 0u;
    }
    __syncthreads();

    // ---- GEMM setup: warp = 16-row strip, full n=64 ----
    const int i0 = wid * 16;
    const int sbase = i0 & 64;
    const int qr = lane >> 2;          // l/4
    const int qc = (lane & 3) * 2;     // (l%4)*2

    float oacc[8][4];
    #pragma unroll
    for (int nb = 0; nb < 8; nb++) {
        float b0 = bias[nb * 8 + qc];
        float b1 = bias[nb * 8 + qc + 1];
        oacc[nb][0] = b0; oacc[nb][1] = b1; oacc[nb][2] = b0; oacc[nb][3] = b1;
    }

    const uint32_t sbu = smem_u32(smem);
    const uint32_t hrow = (uint32_t)(sbase + ((lane >> 3) & 1) * 8 + (lane & 7));
    const uint32_t hrow_off = hrow * 256;
    const uint32_t cb = (uint32_t)(lane >> 4);
    const uint32_t l7 = (uint32_t)(lane & 7);

    for (int g = 0; g < 16; g++) {
        if (flag[g] == 0u) continue;

        unsigned long long m0 = bm[g * 128 + i0 + qr];
        unsigned long long m1 = bm[g * 128 + i0 + 8 + qr];

        // ---- stage 1: S = M_g @ (H_hi + H_lo), fp32 accum in regs ----
        float sacc[16][4];
        #pragma unroll
        for (int t = 0; t < 16; t++) {
            sacc[t][0] = 0.f; sacc[t][1] = 0.f; sacc[t][2] = 0.f; sacc[t][3] = 0.f;
        }
        #pragma unroll
        for (int t = 0; t < 4; t++) {
            const int sh = t * 16 + qc;
            uint32_t a0 = mbits(m0 >> sh);
            uint32_t a1 = mbits(m1 >> sh);
            uint32_t a2 = mbits(m0 >> (sh + 8));
            uint32_t a3 = mbits(m1 >> (sh + 8));
            const uint32_t rowoff = hrow_off + (uint32_t)t * 4096;
            #pragma unroll
            for (int hc = 0; hc < 8; hc++) {
                uint32_t ch  = (uint32_t)(hc * 2) + cb;
                uint32_t off = rowoff + (((ch ^ l7)) << 4);
                uint32_t bh0, bh1, bh2, bh3, bl0, bl1, bl2, bl3;
                LDMX4T(bh0, bh1, bh2, bh3, sbu + SM_HHI + off);
                LDMX4T(bl0, bl1, bl2, bl3, sbu + SM_HLO + off);
                MMA_BF16(sacc[2 * hc],     a0, a1, a2, a3, bh0, bh1);
                MMA_BF16(sacc[2 * hc + 1], a0, a1, a2, a3, bh2, bh3);
                MMA_BF16(sacc[2 * hc],     a0, a1, a2, a3, bl0, bl1);
                MMA_BF16(sacc[2 * hc + 1], a0, a1, a2, a3, bl2, bl3);
            }
        }

        // ---- stage 2: out += S @ W_g, 3-term hi/lo; A built in registers ----
        #pragma unroll
        for (int k16 = 0; k16 < 8; k16++) {
            const float c00 = sacc[2 * k16][0],     c01 = sacc[2 * k16][1];
            const float c02 = sacc[2 * k16][2],     c03 = sacc[2 * k16][3];
            const float c10 = sacc[2 * k16 + 1][0], c11 = sacc[2 * k16 + 1][1];
            const float c12 = sacc[2 * k16 + 1][2], c13 = sacc[2 * k16 + 1][3];
            uint32_t ah0 = pack_bf16x2(c00, c01);
            uint32_t ah1 = pack_bf16x2(c02, c03);
            uint32_t ah2 = pack_bf16x2(c10, c11);
            uint32_t ah3 = pack_bf16x2(c12, c13);
            uint32_t al0 = pack_bf16x2(c00 - bflo(ah0), c01 - bfhi(ah0));
            uint32_t al1 = pack_bf16x2(c02 - bflo(ah1), c03 - bfhi(ah1));
            uint32_t al2 = pack_bf16x2(c10 - bflo(ah2), c11 - bfhi(ah2));
            uint32_t al3 = pack_bf16x2(c12 - bflo(ah3), c13 - bfhi(ah3));
            const uint4* wp = g_wfrags + (size_t)((g * 8 + k16) * 8) * 32 + lane;
            #pragma unroll
            for (int nb = 0; nb < 8; nb++) {
                uint4 w = wp[nb * 32];
                MMA_BF16(oacc[nb], ah0, ah1, ah2, ah3, w.x, w.y);  // Shi*Whi
                MMA_BF16(oacc[nb], ah0, ah1, ah2, ah3, w.z, w.w);  // Shi*Wlo
                MMA_BF16(oacc[nb], al0, al1, al2, al3, w.x, w.y);  // Slo*Whi
            }
        }
    }

    // ---- epilogue ----
    float* orow  = out + ((size_t)b * 128 + i0 + qr) * 64 + qc;
    float* orow8 = orow + 8 * 64;
    #pragma unroll
    for (int nb = 0; nb < 8; nb++) {
        *(float2*)(orow  + nb * 8) = make_float2(oacc[nb][0], oacc[nb][1]);
        *(float2*)(orow8 + nb * 8) = make_float2(oacc[nb][2], oacc[nb][3]);
    }
}

extern "C" void kernel_launch(void* const* d_in, const int* in_sizes, int n_in,
                              void* d_out, int out_size)
{
    const float* hidden = (const float*)d_in[0];
    const float* pos    = (const float*)d_in[1];
    const float* weight = (const float*)d_in[2];
    const float* bias   = (const float*)d_in[3];
    float* out = (float*)d_out;

    const int total = in_sizes[0] / 128;     // 16384 rows
    const int grid  = total / 128;           // 128 CTAs (2 scenes each)

    sp_wprep<<<128, 256>>>(weight);

    cudaFuncSetAttribute(sp_main, cudaFuncAttributeMaxDynamicSharedMemorySize, SMEM_TOTAL);
    sp_main<<<grid, TPB, SMEM_TOTAL>>>(hidden, pos, bias, out);
}